// round 17
// baseline (speedup 1.0000x reference)
#include <cuda_runtime.h>
#include <cuda_bf16.h>
#include <cstdint>
#include <math.h>

// S4D as 1024 batched small GEMMs on mma.sync (HMMA, sm_80 baseline).
//
// K[h, 64k+j] = Re( sum_n cc_n * (r_n^64)^k * r_n^j ),  r_n = exp(dtA[h,n]).
// Per head:  D[64x64] = A[64 x 128] * B[64 x 128]^T   (bf16, fp32 accum)
// D = Ahi*Bhi + Ahi*Blo + Alo*Bhi (lo*lo dropped ~2^-18): 12 k16 MMA steps.
//
// R17: TWO heads per CTA, software-pipelined. Phase1: march head0 tiles.
// Phase2 (one barrier-free block): derive+march head1 WHILE MMA0 runs —
// ptxas interleaves the march's fma/cvt chains with MMA0's LDSM/HMMA chains
// (independent pipes & deps), attacking the measured ~18-cyc per-inst
// dependency gap that R16 proved is the binder. Phase3: MMA1. Grid = 512.
// 4 smem tiles (68KB dynamic), 3 CTAs/SM, numerics identical to R14.

#define AST 136   // row stride in halves (272B; LDSM conflict-free)
#define BST 136
#define TILE_BYTES (64 * AST * 2)   // 17408

__device__ __forceinline__ float2 cmul(float2 a, float2 b) {
    return make_float2(fmaf(a.x, b.x, -a.y * b.y), fmaf(a.x, b.y, a.y * b.x));
}
__device__ __forceinline__ void split_pack(float x, float y, uint32_t& hi, uint32_t& lo) {
    asm("cvt.rn.bf16x2.f32 %0, %1, %2;" : "=r"(hi) : "f"(y), "f"(x));
    uint32_t xh, yh;
    asm("prmt.b32 %0, %1, %2, 0x1054;" : "=r"(xh) : "r"(hi), "r"(0));
    asm("prmt.b32 %0, %1, %2, 0x3254;" : "=r"(yh) : "r"(hi), "r"(0));
    float xr = x - __uint_as_float(xh);
    float yr = y - __uint_as_float(yh);
    asm("cvt.rn.bf16x2.f32 %0, %1, %2;" : "=r"(lo) : "f"(yr), "f"(xr));
}
__device__ __forceinline__ uint32_t smem_u32(const void* p) {
    uint32_t a;
    asm("{ .reg .u64 t; cvta.to.shared.u64 t, %1; cvt.u32.u64 %0, t; }" : "=r"(a) : "l"(p));
    return a;
}
__device__ __forceinline__ void sts32(uint32_t addr, uint32_t v) {
    asm volatile("st.shared.b32 [%0], %1;" :: "r"(addr), "r"(v) : "memory");
}
__device__ __forceinline__ void ldsm4(uint32_t* r, uint32_t addr) {
    asm volatile("ldmatrix.sync.aligned.m8n8.x4.shared.b16 {%0,%1,%2,%3}, [%4];"
                 : "=r"(r[0]), "=r"(r[1]), "=r"(r[2]), "=r"(r[3]) : "r"(addr));
}
__device__ __forceinline__ void mma16816(float* c, const uint32_t* a,
                                         uint32_t b0, uint32_t b1) {
    asm("mma.sync.aligned.m16n8k16.row.col.f32.bf16.bf16.f32 "
        "{%0,%1,%2,%3}, {%4,%5,%6,%7}, {%8,%9}, {%0,%1,%2,%3};"
        : "+f"(c[0]), "+f"(c[1]), "+f"(c[2]), "+f"(c[3])
        : "r"(a[0]), "r"(a[1]), "r"(a[2]), "r"(a[3]), "r"(b0), "r"(b1));
}

// derive per-mode constants r = exp(dtA), cc = 2*C*(r-1)/A
__device__ __forceinline__ void derive(float ld, float la, float av, float cv,
                                       float2& r, float2& cc) {
    float dt = expf(ld);
    float ar = -expf(la);
    float x  = ar * dt, th = av * dt;
    float sy, cy; sincosf(th, &sy, &cy);
    float ex = expf(x);
    r = make_float2(ex * cy, ex * sy);
    float den = ar * ar + av * av;
    float c2  = 2.0f * cv / den;
    cc = make_float2(c2 * ((r.x - 1.0f) * ar + r.y * av),
                     c2 * (r.y * ar - (r.x - 1.0f) * av));
}

// march one head's A and B tiles (rows [16wid,16wid+16) of each)
__device__ __forceinline__ void march_head(float2 r, float2 cc, int wid, int lane,
                                           uint32_t sB_a, uint32_t sA_a) {
    float2 r2  = cmul(r, r),   r4  = cmul(r2, r2);
    float2 r8  = cmul(r4, r4), r16 = cmul(r8, r8);
    float2 r32 = cmul(r16, r16);
    float2 R   = cmul(r32, r32);                 // r^64
    // B: U[j] = cc * r^j
    {
        float2 u[4];
        u[0] = cc;
        if (wid & 1) u[0] = cmul(u[0], r16);
        if (wid & 2) u[0] = cmul(u[0], r32);
        u[1] = cmul(u[0], r);
        u[2] = cmul(u[0], r2);
        u[3] = cmul(u[1], r2);
        uint32_t w = sB_a + (16 * wid) * (BST * 2) + 4 * lane;
        #pragma unroll
        for (int it = 0; it < 4; ++it) {
            #pragma unroll
            for (int i = 0; i < 4; ++i) {
                uint32_t hi, lo;
                split_pack(u[i].x, -u[i].y, hi, lo);
                sts32(w + i * (BST * 2), hi);
                sts32(w + i * (BST * 2) + 128, lo);
                u[i] = cmul(u[i], r4);
            }
            w += 4 * (BST * 2);
        }
    }
    // A: V[k] = R^k
    {
        float2 R2  = cmul(R, R),   R4  = cmul(R2, R2);
        float2 R8  = cmul(R4, R4), R16 = cmul(R8, R8);
        float2 v[4];
        v[0] = make_float2(1.0f, 0.0f);
        if (wid & 1) v[0] = R16;
        if (wid & 2) {
            float2 R32 = cmul(R16, R16);
            v[0] = cmul(v[0], R32);
        }
        v[1] = cmul(v[0], R);
        v[2] = cmul(v[0], R2);
        v[3] = cmul(v[1], R2);
        uint32_t w = sA_a + (16 * wid) * (AST * 2) + 4 * lane;
        #pragma unroll
        for (int it = 0; it < 4; ++it) {
            #pragma unroll
            for (int i = 0; i < 4; ++i) {
                uint32_t hi, lo;
                split_pack(v[i].x, v[i].y, hi, lo);
                sts32(w + i * (AST * 2), hi);
                sts32(w + i * (AST * 2) + 128, lo);
                v[i] = cmul(v[i], R4);
            }
            w += 4 * (AST * 2);
        }
    }
}

// full 12-step split MMA for one head + store
__device__ __forceinline__ void mma_store(uint32_t sA_a, uint32_t sB_a,
                                          float* ob_base, int wid, int lane) {
    const uint32_t aAddr = sA_a + (16 * wid + (lane & 15)) * (AST * 2)
                         + (lane >> 4) * 16;
    const uint32_t bAddr0 = sB_a + (8 * (lane >> 4) + (lane & 7)) * (BST * 2)
                          + ((lane >> 3) & 1) * 16;
    float acc[8][4];
    #pragma unroll
    for (int nt = 0; nt < 8; ++nt)
        #pragma unroll
        for (int e = 0; e < 4; ++e) acc[nt][e] = 0.0f;

    #pragma unroll
    for (int q = 0; q < 4; ++q) {
        const uint32_t qo = 32u * q;
        uint32_t ah[4], bh[4][4];
        ldsm4(ah, aAddr + qo);
        #pragma unroll
        for (int p = 0; p < 4; ++p)
            ldsm4(bh[p], bAddr0 + p * 16 * (BST * 2) + qo);
        #pragma unroll
        for (int nt = 0; nt < 8; ++nt)
            mma16816(acc[nt], ah, bh[nt >> 1][(nt & 1) * 2], bh[nt >> 1][(nt & 1) * 2 + 1]);
        #pragma unroll
        for (int ph = 0; ph < 2; ++ph) {
            uint32_t bl[2][4];
            ldsm4(bl[0], bAddr0 + (2 * ph)     * 16 * (BST * 2) + 128u + qo);
            ldsm4(bl[1], bAddr0 + (2 * ph + 1) * 16 * (BST * 2) + 128u + qo);
            #pragma unroll
            for (int nt = 4 * ph; nt < 4 * ph + 4; ++nt)
                mma16816(acc[nt], ah,
                         bl[(nt >> 1) & 1][(nt & 1) * 2], bl[(nt >> 1) & 1][(nt & 1) * 2 + 1]);
        }
        uint32_t al[4];
        ldsm4(al, aAddr + 128u + qo);
        #pragma unroll
        for (int nt = 0; nt < 8; ++nt)
            mma16816(acc[nt], al, bh[nt >> 1][(nt & 1) * 2], bh[nt >> 1][(nt & 1) * 2 + 1]);
    }

    const int g  = lane >> 2;
    const int tg = lane & 3;
    float* const ob = ob_base + (16 * wid + g) * 64 + 2 * tg;
    #pragma unroll
    for (int nt = 0; nt < 8; ++nt) {
        float* p = ob + 8 * nt;
        *(float2*)p            = make_float2(acc[nt][0], acc[nt][1]);
        *(float2*)(p + 8 * 64) = make_float2(acc[nt][2], acc[nt][3]);
    }
}

__global__ void __launch_bounds__(128, 3)
s4d_mma(float* __restrict__ out,
        const float* __restrict__ C, const float* __restrict__ log_dt,
        const float* __restrict__ lAr, const float* __restrict__ Ai) {
    extern __shared__ __align__(16) unsigned char dynsmem[];
    const uint32_t sA0 = smem_u32(dynsmem);
    const uint32_t sB0 = sA0 + TILE_BYTES;
    const uint32_t sA1 = sB0 + TILE_BYTES;
    const uint32_t sB1 = sA1 + TILE_BYTES;

    const int h0   = 2 * blockIdx.x;
    const int h1   = h0 + 1;
    const int wid  = threadIdx.x >> 5;
    const int lane = threadIdx.x & 31;

    // ---- prefetch both heads' inputs (independent LDGs up front) ----
    const int i0 = h0 * 32 + lane, i1 = i0 + 32;
    float ld0 = log_dt[h0], la0 = lAr[i0], av0 = Ai[i0], cv0 = C[i0];
    float ld1 = log_dt[h1], la1 = lAr[i1], av1 = Ai[i1], cv1 = C[i1];

    // ---- phase 1: head0 derive + march ----
    float2 r0, cc0;
    derive(ld0, la0, av0, cv0, r0, cc0);
    march_head(r0, cc0, wid, lane, sB0, sA0);
    __syncthreads();                       // B0 crosses warps

    // ---- phase 2 (one barrier-free block): head1 derive+march || MMA0 ----
    float2 r1, cc1;
    derive(ld1, la1, av1, cv1, r1, cc1);
    march_head(r1, cc1, wid, lane, sB1, sA1);
    mma_store(sA0, sB0, out + (size_t)h0 * 4096, wid, lane);
    __syncthreads();                       // B1 crosses warps

    // ---- phase 3: MMA1 ----
    mma_store(sA1, sB1, out + (size_t)h1 * 4096, wid, lane);
}

// ---------------- launch ----------------------------------------------------
extern "C" void kernel_launch(void* const* d_in, const int* in_sizes, int n_in,
                              void* d_out, int out_size) {
    const float* C      = (const float*)d_in[0];
    const float* log_dt = (const float*)d_in[1];
    const float* lAr    = (const float*)d_in[2];
    const float* Ai     = (const float*)d_in[3];
    const int H = in_sizes[1];               // 1024

    const int smem = 4 * TILE_BYTES;         // 69632
    cudaFuncSetAttribute(s4d_mma, cudaFuncAttributeMaxDynamicSharedMemorySize, smem);
    s4d_mma<<<H / 2, 128, smem>>>((float*)d_out, C, log_dt, lAr, Ai);
}